// round 1
// baseline (speedup 1.0000x reference)
#include <cuda_runtime.h>
#include <cuda_bf16.h>

#define N_NODES  128
#define N_PAIRS  8128
#define DIM      256
#define NLAYERS  3
#define BATCH    4096
#define NE       131072
#define M_EDGES  (NE + BATCH)   // 135168
#define NEG_SLOPE 0.2f
#define EPS_G     1e-10f

// ---------------- scratch (device globals; no allocation allowed) ----------------
__device__ float          g_h[BATCH * DIM];
__device__ float          g_xa[BATCH * DIM];
__device__ float          g_xb[BATCH * DIM];
__device__ float          g_as[BATCH];
__device__ float          g_ad[BATCH];
__device__ unsigned       g_m[BATCH];          // encoded float for atomicMax
__device__ float          g_s[BATCH];
__device__ float          g_e[M_EDGES];
__device__ float          g_ex[M_EDGES];
__device__ float          g_wdiff[DIM * N_PAIRS];
__device__ float          g_bdiff[N_PAIRS];
__device__ unsigned short g_lut[N_PAIRS];      // p -> (i<<8)|j

// ---------------- prep: Wdiff, bdiff, pair LUT ----------------
__global__ void kPrep(const float* __restrict__ fcW, const float* __restrict__ fcb) {
    int idx = blockIdx.x * blockDim.x + threadIdx.x;
    if (idx < DIM * N_PAIRS) {
        int i = idx / N_PAIRS, p = idx - i * N_PAIRS;
        g_wdiff[idx] = fcW[i * (2 * N_PAIRS) + 2 * p] - fcW[i * (2 * N_PAIRS) + 2 * p + 1];
    }
    if (idx < N_PAIRS) g_bdiff[idx] = fcb[2 * idx] - fcb[2 * idx + 1];
    if (idx < N_NODES - 1) {
        int i = idx;
        int off = i * (N_NODES - 1) - i * (i - 1) / 2;
        for (int j = i + 1; j < N_NODES; j++)
            g_lut[off + j - i - 1] = (unsigned short)((i << 8) | j);
    }
}

// ---------------- layer GEMM: C[4096x256] = A[4096x256] @ B[256x256] ----------------
// BM=128, BN=64, BK=8, TM=8, TN=4, 256 threads
__global__ __launch_bounds__(256) void kGemmLayer(const float* __restrict__ A,
                                                  const float* __restrict__ Bw,
                                                  float* __restrict__ C) {
    __shared__ float As[2][8][128];
    __shared__ float Bs[2][8][64];
    const int K = DIM, N = DIM;
    int tid = threadIdx.x;
    int bm = blockIdx.y * 128, bn = blockIdx.x * 64;
    int tx = tid & 15, ty = tid >> 4;
    int arow = tid >> 1, ak = (tid & 1) * 4;
    int bk = tid >> 4, bc = (tid & 15) * 4;   // only tid<128 loads B

    float acc[8][4];
#pragma unroll
    for (int i = 0; i < 8; i++)
#pragma unroll
        for (int j = 0; j < 4; j++) acc[i][j] = 0.f;

    float4 aReg = *(const float4*)&A[(bm + arow) * K + ak];
    float4 bReg = make_float4(0.f, 0.f, 0.f, 0.f);
    if (tid < 128) bReg = *(const float4*)&Bw[bk * N + bn + bc];

    As[0][ak + 0][arow] = aReg.x;
    As[0][ak + 1][arow] = aReg.y;
    As[0][ak + 2][arow] = aReg.z;
    As[0][ak + 3][arow] = aReg.w;
    if (tid < 128) *(float4*)&Bs[0][bk][bc] = bReg;
    __syncthreads();

    int buf = 0;
#pragma unroll 4
    for (int kt = 0; kt < K / 8; kt++) {
        if (kt < K / 8 - 1) {
            aReg = *(const float4*)&A[(bm + arow) * K + (kt + 1) * 8 + ak];
            if (tid < 128) bReg = *(const float4*)&Bw[((kt + 1) * 8 + bk) * N + bn + bc];
        }
#pragma unroll
        for (int k = 0; k < 8; k++) {
            float4 a0 = *(const float4*)&As[buf][k][ty * 8];
            float4 a1 = *(const float4*)&As[buf][k][ty * 8 + 4];
            float4 b0 = *(const float4*)&Bs[buf][k][tx * 4];
            float av[8] = {a0.x, a0.y, a0.z, a0.w, a1.x, a1.y, a1.z, a1.w};
            float bv[4] = {b0.x, b0.y, b0.z, b0.w};
#pragma unroll
            for (int i = 0; i < 8; i++)
#pragma unroll
                for (int j = 0; j < 4; j++) acc[i][j] += av[i] * bv[j];
        }
        if (kt < K / 8 - 1) {
            As[buf ^ 1][ak + 0][arow] = aReg.x;
            As[buf ^ 1][ak + 1][arow] = aReg.y;
            As[buf ^ 1][ak + 2][arow] = aReg.z;
            As[buf ^ 1][ak + 3][arow] = aReg.w;
            if (tid < 128) *(float4*)&Bs[buf ^ 1][bk][bc] = bReg;
        }
        buf ^= 1;
        __syncthreads();
    }

#pragma unroll
    for (int mi = 0; mi < 8; mi++) {
        int r = bm + ty * 8 + mi;
        float4 v = make_float4(acc[mi][0], acc[mi][1], acc[mi][2], acc[mi][3]);
        *(float4*)&C[r * N + bn + tx * 4] = v;
    }
}

// ---------------- per-row: a_s, a_d, init m/s, zero xout ----------------
__global__ void kRowStats(const float* __restrict__ h, const float* __restrict__ asrc,
                          const float* __restrict__ adst, float* __restrict__ xout) {
    int row = blockIdx.x * 8 + (threadIdx.x >> 5);
    int lane = threadIdx.x & 31;
    float s1 = 0.f, s2 = 0.f;
#pragma unroll
    for (int it = 0; it < 2; it++) {
        int c = it * 128 + lane * 4;
        float4 hv = *(const float4*)&h[row * DIM + c];
        float4 av = *(const float4*)&asrc[c];
        float4 dv = *(const float4*)&adst[c];
        s1 += hv.x * av.x + hv.y * av.y + hv.z * av.z + hv.w * av.w;
        s2 += hv.x * dv.x + hv.y * dv.y + hv.z * dv.z + hv.w * dv.w;
        *(float4*)&xout[row * DIM + c] = make_float4(0.f, 0.f, 0.f, 0.f);
    }
#pragma unroll
    for (int o = 16; o; o >>= 1) {
        s1 += __shfl_xor_sync(0xffffffffu, s1, o);
        s2 += __shfl_xor_sync(0xffffffffu, s2, o);
    }
    if (lane == 0) {
        g_as[row] = s1;
        g_ad[row] = s2;
        g_m[row] = 0x007FFFFFu;   // encoded -inf
        g_s[row] = 0.f;
    }
}

__device__ __forceinline__ unsigned fenc(float v) {
    unsigned b = __float_as_uint(v);
    return (b & 0x80000000u) ? ~b : (b | 0x80000000u);
}
__device__ __forceinline__ float fdec(unsigned k) {
    return (k & 0x80000000u) ? __uint_as_float(k ^ 0x80000000u) : __uint_as_float(~k);
}

// ---------------- edge kernels ----------------
__global__ void kEdgeMax(const int* __restrict__ ei) {
    int idx = blockIdx.x * blockDim.x + threadIdx.x;
    if (idx >= M_EDGES) return;
    int s_ = idx < NE ? ei[idx] : idx - NE;
    int d_ = idx < NE ? ei[NE + idx] : idx - NE;
    float v = g_as[s_] + g_ad[d_];
    v = v > 0.f ? v : NEG_SLOPE * v;
    g_e[idx] = v;
    atomicMax(&g_m[d_], fenc(v));
}

__global__ void kEdgeExp(const int* __restrict__ ei) {
    int idx = blockIdx.x * blockDim.x + threadIdx.x;
    if (idx >= M_EDGES) return;
    int d_ = idx < NE ? ei[NE + idx] : idx - NE;
    float mv = fdec(g_m[d_]);
    float ex = expf(g_e[idx] - mv);
    g_ex[idx] = ex;
    atomicAdd(&g_s[d_], ex);
}

// one warp per edge: xout[dst] += alpha * h[src]   (vector red)
__global__ void kScatter(const int* __restrict__ ei, const float* __restrict__ h,
                         float* __restrict__ xout) {
    int w = (blockIdx.x * blockDim.x + threadIdx.x) >> 5;
    int lane = threadIdx.x & 31;
    if (w >= M_EDGES) return;
    int s_ = w < NE ? ei[w] : w - NE;
    int d_ = w < NE ? ei[NE + w] : w - NE;
    float alpha = g_ex[w] / g_s[d_];
#pragma unroll
    for (int it = 0; it < 2; it++) {
        int c = it * 128 + lane * 4;
        float4 hv = *(const float4*)&h[s_ * DIM + c];
        float* p = &xout[d_ * DIM + c];
        asm volatile("red.global.add.v4.f32 [%0], {%1,%2,%3,%4};"
                     :: "l"(p), "f"(alpha * hv.x), "f"(alpha * hv.y),
                        "f"(alpha * hv.z), "f"(alpha * hv.w)
                     : "memory");
    }
}

__global__ void kBias(float* __restrict__ xout, const float* __restrict__ gb) {
    int idx = blockIdx.x * blockDim.x + threadIdx.x;
    if (idx < BATCH * DIM) xout[idx] += gb[idx & (DIM - 1)];
}

// ---------------- final FC + gumbel + upper-triangle write ----------------
// C = A[4096x256] @ Wdiff[256x8128]; BM=128, BN=128, BK=8, TM=TN=8, 256 threads
__global__ __launch_bounds__(256, 2) void kGemmFC(const float* __restrict__ A,
                                                  const float* __restrict__ gumb,
                                                  float* __restrict__ out) {
    __shared__ float As[2][8][128];
    __shared__ float Bs[2][8][128];
    const int K = DIM, N = N_PAIRS;
    int tid = threadIdx.x;
    int bm = blockIdx.y * 128, bn = blockIdx.x * 128;
    int tx = tid & 15, ty = tid >> 4;
    int arow = tid >> 1, ak = (tid & 1) * 4;
    int bk = tid >> 5, bc = (tid & 31) * 4;
    int bcol = bn + bc;
    bool bok = (bcol < N);

    float acc[8][8];
#pragma unroll
    for (int i = 0; i < 8; i++)
#pragma unroll
        for (int j = 0; j < 8; j++) acc[i][j] = 0.f;

    float4 aReg = *(const float4*)&A[(bm + arow) * K + ak];
    float4 bReg = make_float4(0.f, 0.f, 0.f, 0.f);
    if (bok) bReg = *(const float4*)&g_wdiff[bk * N + bcol];

    As[0][ak + 0][arow] = aReg.x;
    As[0][ak + 1][arow] = aReg.y;
    As[0][ak + 2][arow] = aReg.z;
    As[0][ak + 3][arow] = aReg.w;
    *(float4*)&Bs[0][bk][bc] = bReg;
    __syncthreads();

    int buf = 0;
#pragma unroll 2
    for (int kt = 0; kt < K / 8; kt++) {
        if (kt < K / 8 - 1) {
            aReg = *(const float4*)&A[(bm + arow) * K + (kt + 1) * 8 + ak];
            if (bok) bReg = *(const float4*)&g_wdiff[((kt + 1) * 8 + bk) * N + bcol];
        }
#pragma unroll
        for (int k = 0; k < 8; k++) {
            float4 a0 = *(const float4*)&As[buf][k][ty * 8];
            float4 a1 = *(const float4*)&As[buf][k][ty * 8 + 4];
            float4 b0 = *(const float4*)&Bs[buf][k][tx * 8];
            float4 b1 = *(const float4*)&Bs[buf][k][tx * 8 + 4];
            float av[8] = {a0.x, a0.y, a0.z, a0.w, a1.x, a1.y, a1.z, a1.w};
            float bv[8] = {b0.x, b0.y, b0.z, b0.w, b1.x, b1.y, b1.z, b1.w};
#pragma unroll
            for (int i = 0; i < 8; i++)
#pragma unroll
                for (int j = 0; j < 8; j++) acc[i][j] += av[i] * bv[j];
        }
        if (kt < K / 8 - 1) {
            As[buf ^ 1][ak + 0][arow] = aReg.x;
            As[buf ^ 1][ak + 1][arow] = aReg.y;
            As[buf ^ 1][ak + 2][arow] = aReg.z;
            As[buf ^ 1][ak + 3][arow] = aReg.w;
            *(float4*)&Bs[buf ^ 1][bk][bc] = bReg;
        }
        buf ^= 1;
        __syncthreads();
    }

    // epilogue: gumbel + sign decision, write upper triangle
#pragma unroll
    for (int mi = 0; mi < 8; mi++) {
        int r = bm + ty * 8 + mi;
        int p0 = bn + tx * 8;
        float2 up[8];
        if (p0 + 7 < N) {
            const float4* gp = (const float4*)&gumb[((size_t)r * N_PAIRS + p0) * 2];
#pragma unroll
            for (int q = 0; q < 4; q++) {
                float4 t = gp[q];
                up[2 * q]     = make_float2(t.x, t.y);
                up[2 * q + 1] = make_float2(t.z, t.w);
            }
        } else {
#pragma unroll
            for (int ni = 0; ni < 8; ni++) {
                if (p0 + ni < N)
                    up[ni] = *(const float2*)&gumb[((size_t)r * N_PAIRS + p0 + ni) * 2];
                else
                    up[ni] = make_float2(0.5f, 0.5f);
            }
        }
#pragma unroll
        for (int ni = 0; ni < 8; ni++) {
            int p = p0 + ni;
            if (p < N) {
                float g0 = -__logf(-__logf(up[ni].x + EPS_G) + EPS_G);
                float g1 = -__logf(-__logf(up[ni].y + EPS_G) + EPS_G);
                float t = acc[mi][ni] + g_bdiff[p] + g0 - g1;
                unsigned short lv = g_lut[p];
                int i = lv >> 8, j = lv & 255;
                out[(size_t)r * (N_NODES * N_NODES) + i * N_NODES + j] = (t >= 0.f) ? 1.f : 0.f;
            }
        }
    }
}

// ---------------- mirror lower triangle + zero diagonal (smem transpose) ----------------
__global__ void kMirror(float* __restrict__ out) {
    const int TI[10] = {0, 0, 0, 0, 1, 1, 1, 2, 2, 3};
    const int TJ[10] = {0, 1, 2, 3, 1, 2, 3, 2, 3, 3};
    int b = blockIdx.y;
    int ti = TI[blockIdx.x], tj = TJ[blockIdx.x];
    __shared__ float t[32][33];
    int x = threadIdx.x, y0 = threadIdx.y;   // 32 x 8
    float* base = out + (size_t)b * (N_NODES * N_NODES);
    for (int yy = y0; yy < 32; yy += 8) {
        t[yy][x] = base[(32 * ti + yy) * N_NODES + 32 * tj + x];
    }
    __syncthreads();
    if (ti == tj) {
        for (int yy = y0; yy < 32; yy += 8) {
            int outr = 32 * tj + yy, outc = 32 * ti + x;
            if (yy > x)       base[outr * N_NODES + outc] = t[x][yy];
            else if (yy == x) base[outr * N_NODES + outc] = 0.f;
        }
    } else {
        for (int yy = y0; yy < 32; yy += 8) {
            base[(32 * tj + yy) * N_NODES + 32 * ti + x] = t[x][yy];
        }
    }
}

// ---------------- launch ----------------
extern "C" void kernel_launch(void* const* d_in, const int* in_sizes, int n_in,
                              void* d_out, int out_size) {
    const float* x    = (const float*)d_in[0];
    const int*   ei   = (const int*)d_in[1];
    const float* gu   = (const float*)d_in[2];
    const float* gW   = (const float*)d_in[3];
    const float* gasv = (const float*)d_in[4];
    const float* gadv = (const float*)d_in[5];
    const float* gb   = (const float*)d_in[6];
    const float* fcW  = (const float*)d_in[7];
    const float* fcb  = (const float*)d_in[8];
    float* out = (float*)d_out;

    float *ph, *pxa, *pxb;
    cudaGetSymbolAddress((void**)&ph,  g_h);
    cudaGetSymbolAddress((void**)&pxa, g_xa);
    cudaGetSymbolAddress((void**)&pxb, g_xb);

    kPrep<<<(DIM * N_PAIRS + 255) / 256, 256>>>(fcW, fcb);

    const float* xin = x;
    float* bufs[2] = {pxa, pxb};
    for (int l = 0; l < NLAYERS; l++) {
        float* xout = bufs[l & 1];
        kGemmLayer<<<dim3(DIM / 64, BATCH / 128), 256>>>(xin, gW + l * DIM * DIM, ph);
        kRowStats<<<BATCH / 8, 256>>>(ph, gasv + l * DIM, gadv + l * DIM, xout);
        kEdgeMax<<<(M_EDGES + 255) / 256, 256>>>(ei);
        kEdgeExp<<<(M_EDGES + 255) / 256, 256>>>(ei);
        kScatter<<<M_EDGES / 8, 256>>>(ei, ph, xout);
        kBias<<<(BATCH * DIM) / 256, 256>>>(xout, gb + l * DIM);
        xin = xout;
    }
    kGemmFC<<<dim3((N_PAIRS + 127) / 128, BATCH / 128), 256>>>(xin, gu, out);
    kMirror<<<dim3(10, BATCH), dim3(32, 8)>>>(out);
}